// round 9
// baseline (speedup 1.0000x reference)
#include <cuda_runtime.h>
#include <cuda_fp16.h>
#include <mma.h>
#include <cstdint>

using namespace nvcuda;

#define N_NODES 100000
#define N_EDGES 640000
#define WID     128
#define NFEAT   64
#define KE      192      // WID + NFEAT
#define KM      256      // 2*WID

// ---- edge kernel smem layout (bytes) ----
#define A1_LD 136
#define A2_LD 72
#define B_LD  136
#define C_LD  132
#define SDIFF_BYTES (128*A1_LD*2)
#define SFEAT_BYTES (128*A2_LD*2)
#define SB_E_BYTES  (KE*B_LD*2)
#define SMEM_EDGE   (SDIFF_BYTES + SFEAT_BYTES + SB_E_BYTES)   // 105472 -> 2 blocks/SM

// ---- node kernel smem: sA [128][264]h (sC overlays) + sB chunk [128][136]h ----
#define A_LD_N  264
#define SA_N_BYTES (128*A_LD_N*2)                 // 67584 (== 128*C_LD*4, exact C overlay)
#define SMEM_NODE (SA_N_BYTES + 128*B_LD*2)       // 102400 -> 2 blocks/SM

#define HNEG_INF2 0xFC00FC00u   // packed f16x2 (-inf, -inf)

// ---------- scratch (device globals) ----------
__device__ unsigned g_maxes[(size_t)N_NODES * (WID/2)];   // 25.6 MB, f16x2 per word
__device__ __align__(16) __half g_xh[(size_t)N_NODES * WID];  // 25.6 MB fp16 x image
__device__ __half   g_We[KE * WID];
__device__ __half   g_Wm[KM * WID];

// 8-wide packed-half reduction: one 16-byte RED covering 8 consecutive halves
__device__ __forceinline__ void red_max_h8(unsigned* addr, unsigned p0, unsigned p1,
                                           unsigned p2, unsigned p3) {
    asm volatile("red.global.v4.f16x2.max.noftz [%0], {%1, %2, %3, %4};"
                 :: "l"(addr), "r"(p0), "r"(p1), "r"(p2), "r"(p3) : "memory");
}
// replace any -inf f16 half with +0
__device__ __forceinline__ unsigned fix_neginf(unsigned v) {
    if ((v & 0xFFFFu) == 0xFC00u) v &= 0xFFFF0000u;
    if ((v >> 16)     == 0xFC00u) v &= 0x0000FFFFu;
    return v;
}

// ---------- kernel 0: weights+x -> fp16, reset segment-max buffer ----------
__global__ void prep_kernel(const float* __restrict__ x,
                            const float* __restrict__ We, const float* __restrict__ Wm) {
    int i = blockIdx.x * blockDim.x + threadIdx.x;
    if (i < N_NODES * WID / 4) {
        float4 v = ((const float4*)x)[i];
        __half2 h0 = __floats2half2_rn(v.x, v.y);
        __half2 h1 = __floats2half2_rn(v.z, v.w);
        ((uint2*)g_xh)[i] = make_uint2(*(unsigned*)&h0, *(unsigned*)&h1);
    }
    if (i < N_NODES * (WID/2) / 4)
        ((uint4*)g_maxes)[i] = make_uint4(HNEG_INF2, HNEG_INF2, HNEG_INF2, HNEG_INF2);
    if (i < KE * WID) g_We[i] = __float2half_rn(We[i]);
    if (i < KM * WID) g_Wm[i] = __float2half_rn(Wm[i]);
}

// ---------- kernel 1: fused edge MLP + segment-max ----------
// block = 256 threads, tile = 128 edges x 128 out, K = 192
__global__ __launch_bounds__(256, 2)
void edge_kernel(const int* __restrict__ e, const float* __restrict__ efeat,
                 const float* __restrict__ b_edge) {
    extern __shared__ __align__(16) char smem[];
    __half* sDiff = (__half*)smem;                                // [128][A1_LD]
    __half* sFeat = (__half*)(smem + SDIFF_BYTES);                // [128][A2_LD]
    __half* sB    = (__half*)(smem + SDIFF_BYTES + SFEAT_BYTES);  // [KE][B_LD]
    float*  sC    = (float*)(smem + SDIFF_BYTES);                 // overlays sFeat+sB (dead post-GEMM)
    __shared__ int s_dst[128];

    const int tid  = threadIdx.x;
    const int lane = tid & 31;
    const int wid  = tid >> 5;           // 0..7
    const int ebase = blockIdx.x * 128;

    // stage W_edge (fp16): KE*WID halves = KE*16 uint4
    {
        const uint4* gB = (const uint4*)g_We;
        for (int i = tid; i < KE * 16; i += 256) {
            int k = i >> 4, c = i & 15;
            *((uint4*)(sB + k * B_LD) + c) = gB[i];
        }
    }

    // front-batch edge indices (contiguous, high MLP)
    int srcs[16], dsts[16];
    #pragma unroll
    for (int it = 0; it < 16; ++it) {
        int eidx = ebase + wid * 16 + it;
        srcs[it] = e[eidx];
        dsts[it] = e[N_EDGES + eidx];
    }

    // gather: sDiff = xh[dst]-xh[src] (fp16); sFeat = fp16(e_feat)
    const uint2*  xh = (const uint2*)g_xh;       // 32 uint2 per row
    const float4* f4 = (const float4*)efeat;
    #pragma unroll 4
    for (int it = 0; it < 16; ++it) {
        int r = wid * 16 + it;
        uint2 a = xh[(size_t)dsts[it] * 32 + lane];
        uint2 b = xh[(size_t)srcs[it] * 32 + lane];
        __half2 d0 = __hsub2(*(__half2*)&a.x, *(__half2*)&b.x);
        __half2 d1 = __hsub2(*(__half2*)&a.y, *(__half2*)&b.y);
        *(uint2*)(sDiff + r * A1_LD + lane * 4) =
            make_uint2(*(unsigned*)&d0, *(unsigned*)&d1);
        if (lane < 16) {
            float4 f = f4[(size_t)(ebase + r) * 16 + lane];
            __half2* frow = (__half2*)(sFeat + r * A2_LD);
            frow[lane * 2 + 0] = __floats2half2_rn(f.x, f.y);
            frow[lane * 2 + 1] = __floats2half2_rn(f.z, f.w);
        }
        if (lane == 0) s_dst[r] = dsts[it];
    }
    __syncthreads();

    // GEMM: warp (wm, wn) computes 32x64; K split: diffs (8 steps) + feat (4 steps)
    const int wm = wid & 3, wn = wid >> 2;
    wmma::fragment<wmma::accumulator, 16, 16, 16, float> c[2][4];
    #pragma unroll
    for (int i = 0; i < 2; i++)
        #pragma unroll
        for (int j = 0; j < 4; j++) wmma::fill_fragment(c[i][j], 0.0f);

    #pragma unroll
    for (int k = 0; k < 12; ++k) {
        wmma::fragment<wmma::matrix_a, 16, 16, 16, __half, wmma::row_major> a[2];
        if (k < 8) {
            wmma::load_matrix_sync(a[0], sDiff + (wm * 32 +  0) * A1_LD + k * 16, A1_LD);
            wmma::load_matrix_sync(a[1], sDiff + (wm * 32 + 16) * A1_LD + k * 16, A1_LD);
        } else {
            wmma::load_matrix_sync(a[0], sFeat + (wm * 32 +  0) * A2_LD + (k - 8) * 16, A2_LD);
            wmma::load_matrix_sync(a[1], sFeat + (wm * 32 + 16) * A2_LD + (k - 8) * 16, A2_LD);
        }
        #pragma unroll
        for (int j = 0; j < 4; j++) {
            wmma::fragment<wmma::matrix_b, 16, 16, 16, __half, wmma::row_major> b;
            wmma::load_matrix_sync(b, sB + (k * 16) * B_LD + wn * 64 + j * 16, B_LD);
            wmma::mma_sync(c[0][j], a[0], b, c[0][j]);
            wmma::mma_sync(c[1][j], a[1], b, c[1][j]);
        }
    }
    __syncthreads();   // everyone done reading sFeat/sB before C overlays them

    #pragma unroll
    for (int i = 0; i < 2; i++)
        #pragma unroll
        for (int j = 0; j < 4; j++)
            wmma::store_matrix_sync(sC + (wm * 32 + i * 16) * C_LD + wn * 64 + j * 16,
                                    c[i][j], C_LD, wmma::mem_row_major);
    __syncthreads();

    // epilogue: ef = diffs + relu(C + b); ONE 16-byte red.v4.f16x2 per row per lane-group
    // lanes 0-15 -> even row of pair, lanes 16-31 -> odd row; each lane covers 8 cols
    {
        const int l16 = lane & 15;
        float4 ba = ((const float4*)b_edge)[l16 * 2 + 0];
        float4 bb = ((const float4*)b_edge)[l16 * 2 + 1];
        #pragma unroll
        for (int it = 0; it < 8; ++it) {
            int m = wid * 16 + it * 2 + (lane >> 4);
            unsigned aidx = (unsigned)s_dst[m] * 64u + l16 * 4;
            const float* crow = sC + m * C_LD + l16 * 8;
            float4 c0 = *(const float4*)(crow);
            float4 c1 = *(const float4*)(crow + 4);
            uint4 dv = *(const uint4*)(sDiff + m * A1_LD + l16 * 8);
            __half2 d0 = *(__half2*)&dv.x, d1 = *(__half2*)&dv.y;
            __half2 d2 = *(__half2*)&dv.z, d3 = *(__half2*)&dv.w;
            float v0 = fmaxf(c0.x + ba.x, 0.0f) + __low2float(d0);
            float v1 = fmaxf(c0.y + ba.y, 0.0f) + __high2float(d0);
            float v2 = fmaxf(c0.z + ba.z, 0.0f) + __low2float(d1);
            float v3 = fmaxf(c0.w + ba.w, 0.0f) + __high2float(d1);
            float v4 = fmaxf(c1.x + bb.x, 0.0f) + __low2float(d2);
            float v5 = fmaxf(c1.y + bb.y, 0.0f) + __high2float(d2);
            float v6 = fmaxf(c1.z + bb.z, 0.0f) + __low2float(d3);
            float v7 = fmaxf(c1.w + bb.w, 0.0f) + __high2float(d3);
            __half2 p0 = __floats2half2_rn(v0, v1);
            __half2 p1 = __floats2half2_rn(v2, v3);
            __half2 p2 = __floats2half2_rn(v4, v5);
            __half2 p3 = __floats2half2_rn(v6, v7);
            red_max_h8(&g_maxes[aidx], *(unsigned*)&p0, *(unsigned*)&p1,
                       *(unsigned*)&p2, *(unsigned*)&p3);
        }
    }
}

// ---------- kernel 2: node MLP + residual (split-K B staging -> occ 2) ----------
__global__ __launch_bounds__(256, 2)
void node_kernel(const float* __restrict__ x, const float* __restrict__ b_mlp,
                 float* __restrict__ out) {
    extern __shared__ __align__(16) char smem[];
    __half* sA = (__half*)smem;                      // [128][A_LD_N]
    __half* sB = (__half*)(smem + SA_N_BYTES);       // [128][B_LD] (one K-chunk)
    float*  sC = (float*)smem;                       // [128][C_LD] overlays sA (dead post-GEMM)

    const int tid  = threadIdx.x;
    const int lane = tid & 31;
    const int wid  = tid >> 5;
    const int nbase = blockIdx.x * 128;
    const int wm = wid & 3, wn = wid >> 2;

    // stage B chunk 0 (W_mlp rows 0..127)
    {
        const uint4* gB = (const uint4*)g_Wm;
        for (int i = tid; i < 128 * 16; i += 256) {
            int k = i >> 4, c = i & 15;
            *((uint4*)(sB + k * B_LD) + c) = gB[i];
        }
    }

    // stage A: cols 0..127 = xh (fp16 image), 128..255 = maxes (fp16)
    const uint2* xh = (const uint2*)g_xh;
    #pragma unroll 4
    for (int it = 0; it < 16; ++it) {
        int r = wid * 16 + it;
        int node = nbase + r;
        if (node < N_NODES) {
            *(uint2*)(sA + r * A_LD_N + lane * 4) = xh[(size_t)node * 32 + lane];
            uint2 mv = ((const uint2*)g_maxes)[(size_t)node * 32 + lane];
            *(uint2*)(sA + r * A_LD_N + 128 + lane * 4) =
                make_uint2(fix_neginf(mv.x), fix_neginf(mv.y));
        } else {
            *(uint2*)(sA + r * A_LD_N + lane * 4) = make_uint2(0u, 0u);
            *(uint2*)(sA + r * A_LD_N + 128 + lane * 4) = make_uint2(0u, 0u);
        }
    }
    __syncthreads();

    wmma::fragment<wmma::accumulator, 16, 16, 16, float> c[2][4];
    #pragma unroll
    for (int i = 0; i < 2; i++)
        #pragma unroll
        for (int j = 0; j < 4; j++) wmma::fill_fragment(c[i][j], 0.0f);

    // GEMM chunk 0: A cols 0..127 (x part), B chunk 0
    #pragma unroll
    for (int k = 0; k < 8; ++k) {
        wmma::fragment<wmma::matrix_a, 16, 16, 16, __half, wmma::row_major> a[2];
        wmma::load_matrix_sync(a[0], sA + (wm * 32 +  0) * A_LD_N + k * 16, A_LD_N);
        wmma::load_matrix_sync(a[1], sA + (wm * 32 + 16) * A_LD_N + k * 16, A_LD_N);
        #pragma unroll
        for (int j = 0; j < 4; j++) {
            wmma::fragment<wmma::matrix_b, 16, 16, 16, __half, wmma::row_major> b;
            wmma::load_matrix_sync(b, sB + (k * 16) * B_LD + wn * 64 + j * 16, B_LD);
            wmma::mma_sync(c[0][j], a[0], b, c[0][j]);
            wmma::mma_sync(c[1][j], a[1], b, c[1][j]);
        }
    }
    __syncthreads();   // chunk-0 reads done

    // stage B chunk 1 (W_mlp rows 128..255)
    {
        const uint4* gB = (const uint4*)g_Wm + 128 * 16;
        for (int i = tid; i < 128 * 16; i += 256) {
            int k = i >> 4, c = i & 15;
            *((uint4*)(sB + k * B_LD) + c) = gB[i];
        }
    }
    __syncthreads();

    // GEMM chunk 1: A cols 128..255 (maxes part), B chunk 1
    #pragma unroll
    for (int k = 0; k < 8; ++k) {
        wmma::fragment<wmma::matrix_a, 16, 16, 16, __half, wmma::row_major> a[2];
        wmma::load_matrix_sync(a[0], sA + (wm * 32 +  0) * A_LD_N + 128 + k * 16, A_LD_N);
        wmma::load_matrix_sync(a[1], sA + (wm * 32 + 16) * A_LD_N + 128 + k * 16, A_LD_N);
        #pragma unroll
        for (int j = 0; j < 4; j++) {
            wmma::fragment<wmma::matrix_b, 16, 16, 16, __half, wmma::row_major> b;
            wmma::load_matrix_sync(b, sB + (k * 16) * B_LD + wn * 64 + j * 16, B_LD);
            wmma::mma_sync(c[0][j], a[0], b, c[0][j]);
            wmma::mma_sync(c[1][j], a[1], b, c[1][j]);
        }
    }
    __syncthreads();   // sA reads done before C overlays it

    #pragma unroll
    for (int i = 0; i < 2; i++)
        #pragma unroll
        for (int j = 0; j < 4; j++)
            wmma::store_matrix_sync(sC + (wm * 32 + i * 16) * C_LD + wn * 64 + j * 16,
                                    c[i][j], C_LD, wmma::mem_row_major);
    __syncthreads();

    // epilogue: out = x + relu(C + b_mlp); residual from original f32 x
    {
        float4 bv = ((const float4*)b_mlp)[lane];
        #pragma unroll 4
        for (int it = 0; it < 16; ++it) {
            int m = wid * 16 + it;
            int node = nbase + m;
            if (node >= N_NODES) continue;
            const float* crow = sC + m * C_LD + lane * 4;
            float4 xv = ((const float4*)x)[(size_t)node * 32 + lane];
            float4 o;
            o.x = xv.x + fmaxf(crow[0] + bv.x, 0.0f);
            o.y = xv.y + fmaxf(crow[1] + bv.y, 0.0f);
            o.z = xv.z + fmaxf(crow[2] + bv.z, 0.0f);
            o.w = xv.w + fmaxf(crow[3] + bv.w, 0.0f);
            ((float4*)out)[(size_t)node * 32 + lane] = o;
        }
    }
}

extern "C" void kernel_launch(void* const* d_in, const int* in_sizes, int n_in,
                              void* d_out, int out_size) {
    const float* x     = (const float*)d_in[0];
    const int*   e     = (const int*)d_in[1];
    const float* efeat = (const float*)d_in[2];
    const float* We    = (const float*)d_in[3];
    const float* be    = (const float*)d_in[4];
    const float* Wm    = (const float*)d_in[5];
    const float* bm    = (const float*)d_in[6];
    float* out = (float*)d_out;

    cudaFuncSetAttribute(edge_kernel, cudaFuncAttributeMaxDynamicSharedMemorySize, SMEM_EDGE);
    cudaFuncSetAttribute(node_kernel, cudaFuncAttributeMaxDynamicSharedMemorySize, SMEM_NODE);

    prep_kernel<<<(N_NODES * WID / 4 + 255) / 256, 256>>>(x, We, Wm);
    edge_kernel<<<N_EDGES / 128, 256, SMEM_EDGE>>>(e, efeat, be);
    node_kernel<<<(N_NODES + 127) / 128, 256, SMEM_NODE>>>(x, bm, out);
}